// round 5
// baseline (speedup 1.0000x reference)
#include <cuda_runtime.h>
#include <cuda_fp16.h>
#include <cstdint>

#define NV   200000
#define KOFF 27
#define CA   64
#define CB   128
#define NBLK 256
#define EPSF 1e-5f

// ---------------- device scratch ----------------
__device__ __align__(256) __half g_f0h[(NV + 1) * CA];   // fp16(feats), zero dummy row
__device__ __align__(256) __half g_h1h[(NV + 1) * CB];   // fp16 conv1 out, zero dummy row
__device__ int    g_g2 [KOFF * NV];                      // inverse map, gidx+1 (0 = invalid)
__device__ __align__(256) __half g_w1p[KOFF * 128 * 72];     // bn1-folded w1, [k][n][72]
__device__ __align__(256) __half g_w2p[KOFF * 2 * 128 * 72]; // bn2-folded w2, [k*2+kc][n][72]
__device__ __align__(256) __half g_tb1[128 * 72];            // bias table conv1 [n][72]
__device__ __align__(256) __half g_tb2[128 * 72];            // bias table conv2
__device__ __align__(256) __half g_wnp[128 * 72];            // w_nin [n][72]
__device__ float  g_psum[NBLK * CB];
__device__ float  g_psq [NBLK * CB];
__device__ float  g_sc[2][CB];
__device__ float  g_sh[2][CB];

// ---------------- helpers ----------------
__device__ __forceinline__ uint32_t smem_u32(const void* p) {
    uint32_t a;
    asm("{ .reg .u64 t; cvta.to.shared.u64 t, %1; cvt.u32.u64 %0, t; }" : "=r"(a) : "l"(p));
    return a;
}
__device__ __forceinline__ void mbar_init(uint32_t a, uint32_t c) {
    asm volatile("mbarrier.init.shared.b64 [%0], %1;" :: "r"(a), "r"(c) : "memory");
}
__device__ __forceinline__ void mbar_expect(uint32_t a, uint32_t tx) {
    asm volatile("mbarrier.arrive.expect_tx.shared.b64 _, [%0], %1;" :: "r"(a), "r"(tx) : "memory");
}
__device__ __forceinline__ void mbar_wait(uint32_t a, uint32_t ph) {
    asm volatile(
        "{\n\t.reg .pred P;\n"
        "WL%=:\n\t"
        "mbarrier.try_wait.parity.acquire.cta.shared::cta.b64 P, [%0], %1, 0x989680;\n\t"
        "@P bra WD%=;\n\t"
        "bra WL%=;\n"
        "WD%=:\n\t}"
        :: "r"(a), "r"(ph) : "memory");
}
__device__ __forceinline__ void bulkcp(uint32_t dst, const void* src, uint32_t bytes, uint32_t bar) {
    asm volatile(
        "cp.async.bulk.shared::cta.global.mbarrier::complete_tx::bytes [%0], [%1], %2, [%3];"
        :: "r"(dst), "l"(src), "r"(bytes), "r"(bar) : "memory");
}
__device__ __forceinline__ void sts16(uint32_t addr, uint4 v) {
    asm volatile("st.shared.v4.b32 [%0], {%1,%2,%3,%4};"
                 :: "r"(addr), "r"(v.x), "r"(v.y), "r"(v.z), "r"(v.w) : "memory");
}
__device__ __forceinline__ void ldsm4(uint32_t* d, uint32_t addr) {
    asm volatile("ldmatrix.sync.aligned.m8n8.x4.shared.b16 {%0,%1,%2,%3}, [%4];"
                 : "=r"(d[0]), "=r"(d[1]), "=r"(d[2]), "=r"(d[3]) : "r"(addr));
}
__device__ __forceinline__ void mma16(float* c, const uint32_t* a, const uint32_t* b) {
    asm volatile(
        "mma.sync.aligned.m16n8k16.row.col.f32.f16.f16.f32 "
        "{%0,%1,%2,%3}, {%4,%5,%6,%7}, {%8,%9}, {%0,%1,%2,%3};"
        : "+f"(c[0]), "+f"(c[1]), "+f"(c[2]), "+f"(c[3])
        : "r"(a[0]), "r"(a[1]), "r"(a[2]), "r"(a[3]), "r"(b[0]), "r"(b[1]));
}

// ---------------- BN stats: fp32 input (feats) ----------------
template <int C>
__global__ void k_bn_partial(const float* __restrict__ x) {
    const int C4 = C / 4;
    float4 s = make_float4(0.f, 0.f, 0.f, 0.f);
    float4 q = make_float4(0.f, 0.f, 0.f, 0.f);
    const int tot = NV * C4;
    const int tid = threadIdx.x;
    for (int i = blockIdx.x * 256 + tid; i < tot; i += NBLK * 256) {
        float4 v = ((const float4*)x)[i];
        s.x += v.x; s.y += v.y; s.z += v.z; s.w += v.w;
        q.x += v.x * v.x; q.y += v.y * v.y; q.z += v.z * v.z; q.w += v.w * v.w;
    }
    __shared__ float4 sh[256];
    sh[tid] = s;
    __syncthreads();
    if (tid < C4) {
        float4 a = sh[tid];
        for (int o = C4; o < 256; o += C4) {
            float4 b = sh[tid + o];
            a.x += b.x; a.y += b.y; a.z += b.z; a.w += b.w;
        }
        ((float4*)(g_psum + blockIdx.x * C))[tid] = a;
    }
    __syncthreads();
    sh[tid] = q;
    __syncthreads();
    if (tid < C4) {
        float4 a = sh[tid];
        for (int o = C4; o < 256; o += C4) {
            float4 b = sh[tid + o];
            a.x += b.x; a.y += b.y; a.z += b.z; a.w += b.w;
        }
        ((float4*)(g_psq + blockIdx.x * C))[tid] = a;
    }
}

// ---------------- BN stats: fp16 input (h1h), C = 128 ----------------
__global__ void k_bn_partial_h(const __half* __restrict__ x) {
    float s[8], q[8];
    #pragma unroll
    for (int t = 0; t < 8; ++t) { s[t] = 0.f; q[t] = 0.f; }
    const int tid = threadIdx.x;
    const int tot = NV * 16;
    for (int i = blockIdx.x * 256 + tid; i < tot; i += NBLK * 256) {
        uint4 v = ((const uint4*)x)[i];
        const uint32_t u[4] = {v.x, v.y, v.z, v.w};
        #pragma unroll
        for (int p = 0; p < 4; ++p) {
            float2 f = __half22float2(*(const __half2*)&u[p]);
            s[2 * p] += f.x; s[2 * p + 1] += f.y;
            q[2 * p] += f.x * f.x; q[2 * p + 1] += f.y * f.y;
        }
    }
    __shared__ float sh[256 * 8];
    #pragma unroll
    for (int t = 0; t < 8; ++t) sh[tid * 8 + t] = s[t];
    __syncthreads();
    if (tid < 128) {
        int cb = tid >> 3, ci = tid & 7;
        float a = 0.f;
        #pragma unroll
        for (int j = 0; j < 16; ++j) a += sh[(cb + 16 * j) * 8 + ci];
        g_psum[blockIdx.x * 128 + tid] = a;
    }
    __syncthreads();
    #pragma unroll
    for (int t = 0; t < 8; ++t) sh[tid * 8 + t] = q[t];
    __syncthreads();
    if (tid < 128) {
        int cb = tid >> 3, ci = tid & 7;
        float a = 0.f;
        #pragma unroll
        for (int j = 0; j < 16; ++j) a += sh[(cb + 16 * j) * 8 + ci];
        g_psq[blockIdx.x * 128 + tid] = a;
    }
}

template <int C, int IDX>
__global__ void k_bn_finalize(const float* __restrict__ gamma, const float* __restrict__ beta) {
    const int tid = threadIdx.x;   // blockDim = 4*C
    const int c = tid % C;
    const int qd = tid / C;
    float s = 0.f, s2 = 0.f;
    #pragma unroll 8
    for (int b = qd * (NBLK / 4); b < (qd + 1) * (NBLK / 4); ++b) {
        s  += g_psum[b * C + c];
        s2 += g_psq [b * C + c];
    }
    __shared__ float sha[4 * CB], shb[4 * CB];
    sha[tid] = s; shb[tid] = s2;
    __syncthreads();
    if (qd == 0) {
        s  = sha[c] + sha[C + c] + sha[2 * C + c] + sha[3 * C + c];
        s2 = shb[c] + shb[C + c] + shb[2 * C + c] + shb[3 * C + c];
        float mean = s / (float)NV;
        float var  = s2 / (float)NV - mean * mean;
        float a = rsqrtf(var + EPSF) * gamma[c];
        g_sc[IDX][c] = a;
        g_sh[IDX][c] = beta[c] - mean * a;
    }
}

// ---------------- prep1 ----------------
#define NB_F0  12500          // NV*64/4/256
#define NB_W1P 972            // 27*128*72/256
#define NB_TB  36             // 128*72/256
#define NB_MI  1
#define NB_MAP 21094          // ceil(27*NV/256)
__global__ void k_prep1(const float* __restrict__ feats, const float* __restrict__ w1,
                        const int* __restrict__ gidx, const int* __restrict__ sidx) {
    const int b = blockIdx.x;
    const int tid = threadIdx.x;
    if (b < NB_F0) {
        int i = b * 256 + tid;
        float4 v = ((const float4*)feats)[i];
        ((__half2*)g_f0h)[2 * i]     = __floats2half2_rn(v.x, v.y);
        ((__half2*)g_f0h)[2 * i + 1] = __floats2half2_rn(v.z, v.w);
    } else if (b < NB_F0 + NB_W1P) {
        int i = (b - NB_F0) * 256 + tid;       // 248832
        int k = i / (128 * 72);
        int rem = i - k * (128 * 72);
        int n = rem / 72, c = rem - n * 72;
        g_w1p[i] = __float2half_rn(c < 64 ? g_sc[0][c] * w1[(k * 64 + c) * 128 + n] : 0.f);
    } else if (b < NB_F0 + NB_W1P + NB_TB) {
        int i = (b - NB_F0 - NB_W1P) * 256 + tid;  // 9216
        int n = i / 72, kk = i - n * 72;
        float acc = 0.f;
        if (kk < KOFF)
            for (int c = 0; c < 64; ++c)
                acc += g_sh[0][c] * w1[(kk * 64 + c) * 128 + n];
        g_tb1[i] = __float2half_rn(acc);
    } else if (b < NB_F0 + NB_W1P + NB_TB + NB_MI) {
        if (tid < 32)              ((__half2*)(g_f0h + NV * CA))[tid] = __half2half2(__ushort_as_half(0));
        if (tid >= 32 && tid < 96) ((__half2*)(g_h1h + NV * CB))[tid - 32] = __half2half2(__ushort_as_half(0));
    } else {
        int j = (b - NB_F0 - NB_W1P - NB_TB - NB_MI) * 256 + tid;
        if (j < KOFF * NV) {
            int s = sidx[j];
            if (s < NV) {
                int k = j / NV;
                g_g2[k * NV + s] = gidx[j] + 1;
            }
        }
    }
}

// ---------------- prep2 ----------------
#define NB_W2P 1944           // 27*2*128*72/256
__global__ void k_prep2(const float* __restrict__ w2, const float* __restrict__ wnin) {
    const int b = blockIdx.x;
    const int tid = threadIdx.x;
    if (b < NB_W2P) {
        int i = b * 256 + tid;                 // 497664
        int k2 = i / (128 * 72);               // 0..53  (k27*2 + kc)
        int rem = i - k2 * (128 * 72);
        int n = rem / 72, c = rem - n * 72;
        int k27 = k2 >> 1;
        int cg = (k2 & 1) * 64 + c;
        g_w2p[i] = __float2half_rn(c < 64 ? g_sc[1][cg] * w2[(k27 * 128 + cg) * 128 + n] : 0.f);
    } else if (b < NB_W2P + NB_TB) {
        int i = (b - NB_W2P) * 256 + tid;
        int n = i / 72, kk = i - n * 72;
        float acc = 0.f;
        if (kk < KOFF)
            for (int c = 0; c < 128; ++c)
                acc += g_sh[1][c] * w2[(kk * 128 + c) * 128 + n];
        g_tb2[i] = __float2half_rn(acc);
    } else {
        int i = (b - NB_W2P - NB_TB) * 256 + tid;  // 9216
        int n = i / 72, c = i - n * 72;
        g_wnp[i] = __float2half_rn(c < 64 ? wnin[c * 128 + n] : 0.f);
    }
}

// ---------------- fp16 warp-MMA gather-GEMM conv, bulk-TMA producer ---------
// CTA 256 thr, tile M=128 x N=128; warp: rows (wid&3)*32, cols (wid>>2)*64.
// K chunks of 64; 2-stage ping-pong, loads via cp.async.bulk + mbarrier.
// smem stage: A 128x144B (18432) | B 128x144B (18432). Row stride 144B is
// bank-conflict-free for ldmatrix (lane bank offset = 4*i mod 32).
template <int CIN, bool SKIP, bool OUTH>
__global__ void __launch_bounds__(256, 2)
k_conv(const __half* __restrict__ src, const __half* __restrict__ wtp,
       const __half* __restrict__ tbp, const __half* __restrict__ wnp,
       void* __restrict__ dstv) {
    extern __shared__ __align__(16) char smraw[];
    __shared__ __align__(8) uint64_t s_bars[2];
    int* sIdx = (int*)(smraw + 2 * 36864);
    const uint32_t tile0   = smem_u32(smraw);
    const uint32_t barBase = smem_u32(s_bars);

    const int tid  = threadIdx.x;
    const int lane = tid & 31;
    const int wid  = tid >> 5;
    const int g    = lane >> 2;
    const int tig  = lane & 3;
    const int row0 = blockIdx.x * 128;
    const int warpRow = (wid & 3) * 32;
    const int warpCol = (wid >> 2) * 64;

    constexpr int CPK  = CIN / 64;
    constexpr int MAIN = KOFF * CPK;
    constexpr int CH   = MAIN + (SKIP ? 1 : 0) + 1;

    if (tid == 0) {
        mbar_init(barBase, 1);
        mbar_init(barBase + 8, 1);
    }
    for (int i = tid; i < KOFF * 128; i += 256) {
        int k = i >> 7, r = i & 127;
        int row = row0 + r;
        int v = (row < NV) ? g_g2[k * NV + row] : 0;
        sIdx[i] = v ? (v - 1) : NV;
    }
    __syncthreads();

    const int lr  = tid >> 3;
    const int sub = tid & 7;

    auto fill = [&](int s) {
        const uint32_t aB  = tile0 + (uint32_t)(s & 1) * 36864u;
        const uint32_t bB  = aB + 18432u;
        const uint32_t bar = barBase + (uint32_t)((s & 1) * 8);
        const bool isMask  = (s == CH - 1);
        if (tid == 0) {
            mbar_expect(bar, isMask ? 18432u : 34816u);
            const __half* bsrc;
            if (s < MAIN)            bsrc = wtp + (size_t)s * (128 * 72);
            else if (SKIP && s == MAIN) bsrc = wnp;
            else                     bsrc = tbp;
            bulkcp(bB, bsrc, 18432u, bar);
        }
        if (!isMask && tid < 128) {
            const __half* asrc;
            if (s < MAIN) {
                int k27 = (CPK == 1) ? s : (s >> 1);
                int gg = sIdx[(k27 << 7) + tid];
                asrc = src + (size_t)gg * CIN + ((CPK == 1) ? 0 : ((s & 1) << 6));
            } else {
                int row = row0 + tid;
                int gg = row < NV ? row : NV;
                asrc = g_f0h + (size_t)gg * 64;
            }
            bulkcp(aB + (uint32_t)tid * 144u, asrc, 128u, bar);
        }
    };

    float acc[2][8][4];
    #pragma unroll
    for (int mt = 0; mt < 2; ++mt)
        #pragma unroll
        for (int nt = 0; nt < 8; ++nt)
            #pragma unroll
            for (int q = 0; q < 4; ++q) acc[mt][nt][q] = 0.f;

    // ldmatrix lane address components
    const int s7 = lane & 7;
    const int rowA = warpRow + s7 + ((lane >> 3) & 1) * 8;
    const int uA   = lane >> 4;
    const int rowB = warpCol + s7 + (lane >> 4) * 8;
    const int uB   = (lane >> 3) & 1;

    fill(0);

    for (int s = 0; s < CH; ++s) {
        if (s + 1 < CH) fill(s + 1);
        mbar_wait(barBase + (uint32_t)((s & 1) * 8), (s >> 1) & 1);

        const uint32_t aB = tile0 + (uint32_t)(s & 1) * 36864u;
        const uint32_t bB = aB + 18432u;

        if (s == CH - 1) {
            // bias-mask chunk: A[r][kk] = (kk < 27 && gather valid) ? 1 : 0
            #pragma unroll
            for (int j = 0; j < 4; ++j) {
                int r = lr + j * 32;
                uint4 w;
                uint32_t* wp = (uint32_t*)&w;
                #pragma unroll
                for (int q = 0; q < 4; ++q) {
                    int kk0 = sub * 8 + 2 * q;
                    uint32_t h0 = (kk0 < KOFF && sIdx[(kk0 << 7) + r] != NV) ? 0x3C00u : 0u;
                    uint32_t h1 = (kk0 + 1 < KOFF && sIdx[((kk0 + 1) << 7) + r] != NV) ? 0x3C00u : 0u;
                    wp[q] = h0 | (h1 << 16);
                }
                sts16(aB + (uint32_t)(r * 144 + sub * 16), w);
            }
            __syncthreads();
        }

        const uint32_t pa0 = aB + (uint32_t)(rowA * 144);
        const uint32_t pa1 = aB + (uint32_t)((rowA + 16) * 144);

        #pragma unroll
        for (int ks = 0; ks < 4; ++ks) {
            const int u0 = ks * 2;
            uint32_t a[2][4];
            const uint32_t aoff = (uint32_t)((u0 + uA) << 4);
            ldsm4(a[0], pa0 + aoff);
            ldsm4(a[1], pa1 + aoff);
            uint32_t bfr[4][4];
            const uint32_t boff = (uint32_t)((u0 + uB) << 4);
            #pragma unroll
            for (int p = 0; p < 4; ++p)
                ldsm4(bfr[p], bB + (uint32_t)((rowB + p * 16) * 144) + boff);
            #pragma unroll
            for (int p = 0; p < 4; ++p) {
                mma16(acc[0][2 * p],     a[0], &bfr[p][0]);
                mma16(acc[0][2 * p + 1], a[0], &bfr[p][2]);
                mma16(acc[1][2 * p],     a[1], &bfr[p][0]);
                mma16(acc[1][2 * p + 1], a[1], &bfr[p][2]);
            }
        }
        __syncthreads();
    }

    // epilogue
    #pragma unroll
    for (int mt = 0; mt < 2; ++mt) {
        int r0 = row0 + warpRow + mt * 16 + g;
        #pragma unroll
        for (int nt = 0; nt < 8; ++nt) {
            int col = warpCol + nt * 8 + 2 * tig;
            if (OUTH) {
                __half* dst = (__half*)dstv;
                if (r0 < NV)
                    *(__half2*)(dst + (size_t)r0 * CB + col) =
                        __floats2half2_rn(acc[mt][nt][0], acc[mt][nt][1]);
                if (r0 + 8 < NV)
                    *(__half2*)(dst + (size_t)(r0 + 8) * CB + col) =
                        __floats2half2_rn(acc[mt][nt][2], acc[mt][nt][3]);
            } else {
                float* dst = (float*)dstv;
                if (r0 < NV)
                    *(float2*)(dst + (size_t)r0 * CB + col) =
                        make_float2(acc[mt][nt][0], acc[mt][nt][1]);
                if (r0 + 8 < NV)
                    *(float2*)(dst + (size_t)(r0 + 8) * CB + col) =
                        make_float2(acc[mt][nt][2], acc[mt][nt][3]);
            }
        }
    }
}

// ---------------- launch ----------------
extern "C" void kernel_launch(void* const* d_in, const int* in_sizes, int n_in,
                              void* d_out, int out_size) {
    const float* feats     = (const float*)d_in[0];
    const float* w1        = (const float*)d_in[1];
    const float* w2        = (const float*)d_in[2];
    const float* w_nin     = (const float*)d_in[3];
    const float* bn1_gamma = (const float*)d_in[4];
    const float* bn1_beta  = (const float*)d_in[5];
    const float* bn2_gamma = (const float*)d_in[6];
    const float* bn2_beta  = (const float*)d_in[7];
    const int*   gidx      = (const int*)d_in[8];
    const int*   sidx      = (const int*)d_in[9];
    float*       out       = (float*)d_out;

    const int dynsm = 2 * 36864 + KOFF * 128 * 4;   // 87552 B
    cudaFuncSetAttribute(k_conv<CA, false, true >, cudaFuncAttributeMaxDynamicSharedMemorySize, dynsm);
    cudaFuncSetAttribute(k_conv<CB, true,  false>, cudaFuncAttributeMaxDynamicSharedMemorySize, dynsm);

    __half *f0h, *h1h, *w1p, *w2p, *tb1, *tb2, *wnp;
    cudaGetSymbolAddress((void**)&f0h, g_f0h);
    cudaGetSymbolAddress((void**)&h1h, g_h1h);
    cudaGetSymbolAddress((void**)&w1p, g_w1p);
    cudaGetSymbolAddress((void**)&w2p, g_w2p);
    cudaGetSymbolAddress((void**)&tb1, g_tb1);
    cudaGetSymbolAddress((void**)&tb2, g_tb2);
    cudaGetSymbolAddress((void**)&wnp, g_wnp);

    const int grid = (NV + 127) / 128;   // 1563

    k_bn_partial<CA><<<NBLK, 256>>>(feats);
    k_bn_finalize<CA, 0><<<1, 4 * CA>>>(bn1_gamma, bn1_beta);
    k_prep1<<<NB_F0 + NB_W1P + NB_TB + NB_MI + NB_MAP, 256>>>(feats, w1, gidx, sidx);
    // launch slot #4: conv1 (profiled)
    k_conv<CA, false, true><<<grid, 256, dynsm>>>(f0h, w1p, tb1, nullptr, h1h);
    k_bn_partial_h<<<NBLK, 256>>>(h1h);
    k_bn_finalize<CB, 1><<<1, 4 * CB>>>(bn2_gamma, bn2_beta);
    k_prep2<<<NB_W2P + NB_TB + NB_TB, 256>>>(w2, w_nin);
    k_conv<CB, true, false><<<grid, 256, dynsm>>>(h1h, w2p, tb2, wnp, out);
}

// round 6
// speedup vs baseline: 1.0182x; 1.0182x over previous
#include <cuda_runtime.h>
#include <cuda_fp16.h>
#include <cstdint>

#define NV   200000
#define KOFF 27
#define CA   64
#define CB   128
#define NBLK 256
#define EPSF 1e-5f

// ---------------- device scratch ----------------
__device__ __half g_f0h[(NV + 1) * CA];      // fp16(feats), zero dummy row
__device__ __half g_h1h[(NV + 1) * CB];      // fp16 conv1 out, zero dummy row
__device__ int    g_g2 [KOFF * NV];          // inverse map, stores gidx+1 (0 = invalid)
__device__ __half g_w1h[KOFF * CB * CA];     // fp16( bn1_scale[c] * w1[k][c][n] ) as [k][n][c]
__device__ __half g_w2h[KOFF * CB * CB];     // fp16( bn2_scale[c] * w2[k][c][n] ) as [k][n][c]
__device__ __half g_tb1[CB * 64];            // bias-trick B for conv1: [n][kk], kk<27 used
__device__ __half g_tb2[CB * 64];            // bias-trick B for conv2
__device__ __half g_wnh[CB * 64];            // fp16(w_nin) as [n][c]
__device__ float  g_psum[NBLK * CB];
__device__ float  g_psq [NBLK * CB];
__device__ float  g_sc[2][CB];
__device__ float  g_sh[2][CB];

// ---------------- helpers ----------------
__device__ __forceinline__ uint32_t smem_u32(const void* p) {
    uint32_t a;
    asm("{ .reg .u64 t; cvta.to.shared.u64 t, %1; cvt.u32.u64 %0, t; }" : "=r"(a) : "l"(p));
    return a;
}
__device__ __forceinline__ void cpa16(uint32_t s, const void* g) {
    asm volatile("cp.async.cg.shared.global [%0], [%1], 16;" :: "r"(s), "l"(g));
}
__device__ __forceinline__ void cpa_commit() {
    asm volatile("cp.async.commit_group;" ::: "memory");
}
__device__ __forceinline__ void cpa_wait2() { asm volatile("cp.async.wait_group 2;" ::: "memory"); }
__device__ __forceinline__ void cpa_wait1() { asm volatile("cp.async.wait_group 1;" ::: "memory"); }
__device__ __forceinline__ void cpa_wait0() { asm volatile("cp.async.wait_group 0;" ::: "memory"); }
__device__ __forceinline__ void sts16(uint32_t addr, uint4 v) {
    asm volatile("st.shared.v4.b32 [%0], {%1,%2,%3,%4};"
                 :: "r"(addr), "r"(v.x), "r"(v.y), "r"(v.z), "r"(v.w) : "memory");
}
__device__ __forceinline__ void ldsm4(uint32_t* d, uint32_t addr) {
    asm volatile("ldmatrix.sync.aligned.m8n8.x4.shared.b16 {%0,%1,%2,%3}, [%4];"
                 : "=r"(d[0]), "=r"(d[1]), "=r"(d[2]), "=r"(d[3]) : "r"(addr));
}
__device__ __forceinline__ void mma16(float* c, const uint32_t* a, const uint32_t* b) {
    asm volatile(
        "mma.sync.aligned.m16n8k16.row.col.f32.f16.f16.f32 "
        "{%0,%1,%2,%3}, {%4,%5,%6,%7}, {%8,%9}, {%0,%1,%2,%3};"
        : "+f"(c[0]), "+f"(c[1]), "+f"(c[2]), "+f"(c[3])
        : "r"(a[0]), "r"(a[1]), "r"(a[2]), "r"(a[3]), "r"(b[0]), "r"(b[1]));
}

// ---------------- BN stats: fp32 input (feats) ----------------
template <int C>
__global__ void k_bn_partial(const float* __restrict__ x) {
    const int C4 = C / 4;
    float4 s = make_float4(0.f, 0.f, 0.f, 0.f);
    float4 q = make_float4(0.f, 0.f, 0.f, 0.f);
    const int tot = NV * C4;
    const int tid = threadIdx.x;
    for (int i = blockIdx.x * 256 + tid; i < tot; i += NBLK * 256) {
        float4 v = ((const float4*)x)[i];
        s.x += v.x; s.y += v.y; s.z += v.z; s.w += v.w;
        q.x += v.x * v.x; q.y += v.y * v.y; q.z += v.z * v.z; q.w += v.w * v.w;
    }
    __shared__ float4 sh[256];
    sh[tid] = s;
    __syncthreads();
    if (tid < C4) {
        float4 a = sh[tid];
        for (int o = C4; o < 256; o += C4) {
            float4 b = sh[tid + o];
            a.x += b.x; a.y += b.y; a.z += b.z; a.w += b.w;
        }
        ((float4*)(g_psum + blockIdx.x * C))[tid] = a;
    }
    __syncthreads();
    sh[tid] = q;
    __syncthreads();
    if (tid < C4) {
        float4 a = sh[tid];
        for (int o = C4; o < 256; o += C4) {
            float4 b = sh[tid + o];
            a.x += b.x; a.y += b.y; a.z += b.z; a.w += b.w;
        }
        ((float4*)(g_psq + blockIdx.x * C))[tid] = a;
    }
}

// ---------------- BN stats: fp16 input (h1h), C = 128 ----------------
__global__ void k_bn_partial_h(const __half* __restrict__ x) {
    float s[8], q[8];
    #pragma unroll
    for (int t = 0; t < 8; ++t) { s[t] = 0.f; q[t] = 0.f; }
    const int tid = threadIdx.x;
    const int tot = NV * 16;
    for (int i = blockIdx.x * 256 + tid; i < tot; i += NBLK * 256) {
        uint4 v = ((const uint4*)x)[i];
        const uint32_t u[4] = {v.x, v.y, v.z, v.w};
        #pragma unroll
        for (int p = 0; p < 4; ++p) {
            float2 f = __half22float2(*(const __half2*)&u[p]);
            s[2 * p] += f.x; s[2 * p + 1] += f.y;
            q[2 * p] += f.x * f.x; q[2 * p + 1] += f.y * f.y;
        }
    }
    __shared__ float sh[256 * 8];
    #pragma unroll
    for (int t = 0; t < 8; ++t) sh[tid * 8 + t] = s[t];
    __syncthreads();
    if (tid < 128) {
        int cb = tid >> 3, ci = tid & 7;
        float a = 0.f;
        #pragma unroll
        for (int j = 0; j < 16; ++j) a += sh[(cb + 16 * j) * 8 + ci];
        g_psum[blockIdx.x * 128 + tid] = a;
    }
    __syncthreads();
    #pragma unroll
    for (int t = 0; t < 8; ++t) sh[tid * 8 + t] = q[t];
    __syncthreads();
    if (tid < 128) {
        int cb = tid >> 3, ci = tid & 7;
        float a = 0.f;
        #pragma unroll
        for (int j = 0; j < 16; ++j) a += sh[(cb + 16 * j) * 8 + ci];
        g_psq[blockIdx.x * 128 + tid] = a;
    }
}

template <int C, int IDX>
__global__ void k_bn_finalize(const float* __restrict__ gamma, const float* __restrict__ beta) {
    const int tid = threadIdx.x;   // blockDim = 4*C
    const int c = tid % C;
    const int qd = tid / C;
    float s = 0.f, s2 = 0.f;
    #pragma unroll 8
    for (int b = qd * (NBLK / 4); b < (qd + 1) * (NBLK / 4); ++b) {
        s  += g_psum[b * C + c];
        s2 += g_psq [b * C + c];
    }
    __shared__ float sha[4 * CB], shb[4 * CB];
    sha[tid] = s; shb[tid] = s2;
    __syncthreads();
    if (qd == 0) {
        s  = sha[c] + sha[C + c] + sha[2 * C + c] + sha[3 * C + c];
        s2 = shb[c] + shb[C + c] + shb[2 * C + c] + shb[3 * C + c];
        float mean = s / (float)NV;
        float var  = s2 / (float)NV - mean * mean;
        float a = rsqrtf(var + EPSF) * gamma[c];
        g_sc[IDX][c] = a;
        g_sh[IDX][c] = beta[c] - mean * a;
    }
}

// ---------------- prep1 ----------------
#define NB_F0  12500          // NV*64/4/256
#define NB_W1  864            // 27*128*64/256
#define NB_TB  32             // 128*64/256
#define NB_MI  1
#define NB_MAP 21094          // ceil(27*NV/256)
__global__ void k_prep1(const float* __restrict__ feats, const float* __restrict__ w1,
                        const int* __restrict__ gidx, const int* __restrict__ sidx) {
    const int b = blockIdx.x;
    const int tid = threadIdx.x;
    if (b < NB_F0) {
        int i = b * 256 + tid;
        float4 v = ((const float4*)feats)[i];
        ((__half2*)g_f0h)[2 * i]     = __floats2half2_rn(v.x, v.y);
        ((__half2*)g_f0h)[2 * i + 1] = __floats2half2_rn(v.z, v.w);
    } else if (b < NB_F0 + NB_W1) {
        int i = (b - NB_F0) * 256 + tid;       // 221184
        int k = i >> 13;
        int rem = i & 8191;
        int n = rem >> 6, c = rem & 63;
        g_w1h[i] = __float2half_rn(g_sc[0][c] * w1[(k * 64 + c) * 128 + n]);
    } else if (b < NB_F0 + NB_W1 + NB_TB) {
        int i = (b - NB_F0 - NB_W1) * 256 + tid;  // 8192
        int n = i >> 6, kk = i & 63;
        float acc = 0.f;
        if (kk < KOFF)
            for (int c = 0; c < 64; ++c)
                acc += g_sh[0][c] * w1[(kk * 64 + c) * 128 + n];
        g_tb1[i] = __float2half_rn(acc);
    } else if (b < NB_F0 + NB_W1 + NB_TB + NB_MI) {
        if (tid < 32)              ((__half2*)(g_f0h + NV * CA))[tid] = __half2half2(__ushort_as_half(0));
        if (tid >= 32 && tid < 96) ((__half2*)(g_h1h + NV * CB))[tid - 32] = __half2half2(__ushort_as_half(0));
    } else {
        int j = (b - NB_F0 - NB_W1 - NB_TB - NB_MI) * 256 + tid;
        if (j < KOFF * NV) {
            int s = sidx[j];
            if (s < NV) {
                int k = j / NV;
                g_g2[k * NV + s] = gidx[j] + 1;
            }
        }
    }
}

// ---------------- prep2 ----------------
#define NB_W2  1728           // 27*128*128/256
__global__ void k_prep2(const float* __restrict__ w2, const float* __restrict__ wnin) {
    const int b = blockIdx.x;
    const int tid = threadIdx.x;
    if (b < NB_W2) {
        int i = b * 256 + tid;                 // 442368
        int k = i >> 14;
        int rem = i & 16383;
        int n = rem >> 7, c = rem & 127;
        g_w2h[i] = __float2half_rn(g_sc[1][c] * w2[(k * 128 + c) * 128 + n]);
    } else if (b < NB_W2 + NB_TB) {
        int i = (b - NB_W2) * 256 + tid;
        int n = i >> 6, kk = i & 63;
        float acc = 0.f;
        if (kk < KOFF)
            for (int c = 0; c < 128; ++c)
                acc += g_sh[1][c] * w2[(kk * 128 + c) * 128 + n];
        g_tb2[i] = __float2half_rn(acc);
    } else {
        int i = (b - NB_W2 - NB_TB) * 256 + tid;  // 8192
        int n = i >> 6, c = i & 63;
        g_wnh[i] = __float2half_rn(wnin[c * 128 + n]);
    }
}

// ---------------- fp16 warp-MMA gather-GEMM conv (16 warps, 32x32 tiles) ----
// CTA: 512 thr, tile M=128 x N=128; warp (wid): rows (wid&3)*32, cols (wid>>2)*32.
// K chunks of 64; 3-stage cp.async pipeline; XOR-swizzled smem.
template <int CIN, bool SKIP, bool OUTH>
__global__ void __launch_bounds__(512, 2)
k_conv(const __half* __restrict__ src, const __half* __restrict__ wt,
       const __half* __restrict__ tb, void* __restrict__ dstv) {
    extern __shared__ __align__(16) char smraw[];
    int* sIdx = (int*)(smraw + 3 * 32768);
    const uint32_t tile0 = smem_u32(smraw);

    const int tid  = threadIdx.x;
    const int lane = tid & 31;
    const int wid  = tid >> 5;
    const int g    = lane >> 2;
    const int tig  = lane & 3;
    const int row0 = blockIdx.x * 128;
    const int warpRow = (wid & 3) * 32;
    const int warpCol = (wid >> 2) * 32;

    constexpr int CPK  = CIN / 64;
    constexpr int MAIN = KOFF * CPK;
    constexpr int CH   = MAIN + (SKIP ? 1 : 0) + 1;

    for (int i = tid; i < KOFF * 128; i += 512) {
        int k = i >> 7, r = i & 127;
        int row = row0 + r;
        int v = (row < NV) ? g_g2[k * NV + row] : 0;
        sIdx[i] = v ? (v - 1) : NV;
    }
    __syncthreads();

    const int lr  = tid >> 3;     // 0..63
    const int sub = tid & 7;      // 16B unit

    auto issue = [&](int s) {
        const uint32_t aB = tile0 + (uint32_t)(s % 3) * 32768u;
        const uint32_t bB = aB + 16384u;
        if (s < MAIN) {
            const int k27 = (CPK == 1) ? s : (s >> 1);
            const int kb  = (CPK == 1) ? 0 : ((s & 1) << 6);
            #pragma unroll
            for (int j = 0; j < 2; ++j) {
                int r = lr + j * 64;
                int gg = sIdx[(k27 << 7) + r];
                uint32_t off = (uint32_t)((r << 7) + ((sub ^ (r & 7)) << 4));
                cpa16(aB + off, src + (size_t)gg * CIN + kb + sub * 8);
            }
            const __half* bs = wt + ((size_t)k27 * 128) * CIN + kb;
            #pragma unroll
            for (int j = 0; j < 2; ++j) {
                int n = lr + j * 64;
                uint32_t off = (uint32_t)((n << 7) + ((sub ^ (n & 7)) << 4));
                cpa16(bB + off, bs + (size_t)n * CIN + sub * 8);
            }
        } else if (SKIP && s == MAIN) {
            #pragma unroll
            for (int j = 0; j < 2; ++j) {
                int r = lr + j * 64;
                int row = row0 + r;
                int gg = row < NV ? row : NV;
                uint32_t off = (uint32_t)((r << 7) + ((sub ^ (r & 7)) << 4));
                cpa16(aB + off, g_f0h + (size_t)gg * 64 + sub * 8);
            }
            #pragma unroll
            for (int j = 0; j < 2; ++j) {
                int n = lr + j * 64;
                uint32_t off = (uint32_t)((n << 7) + ((sub ^ (n & 7)) << 4));
                cpa16(bB + off, g_wnh + (size_t)n * 64 + sub * 8);
            }
        } else {
            // bias-mask chunk: A[r][kk] = (kk < 27 && gather valid) ? 1 : 0
            #pragma unroll
            for (int j = 0; j < 2; ++j) {
                int r = lr + j * 64;
                uint4 w;
                uint32_t* wp = (uint32_t*)&w;
                #pragma unroll
                for (int q = 0; q < 4; ++q) {
                    int kk0 = sub * 8 + 2 * q;
                    uint32_t h0 = (kk0 < KOFF && sIdx[(kk0 << 7) + r] != NV) ? 0x3C00u : 0u;
                    uint32_t h1 = (kk0 + 1 < KOFF && sIdx[((kk0 + 1) << 7) + r] != NV) ? 0x3C00u : 0u;
                    wp[q] = h0 | (h1 << 16);
                }
                uint32_t off = (uint32_t)((r << 7) + ((sub ^ (r & 7)) << 4));
                sts16(aB + off, w);
            }
            #pragma unroll
            for (int j = 0; j < 2; ++j) {
                int n = lr + j * 64;
                uint32_t off = (uint32_t)((n << 7) + ((sub ^ (n & 7)) << 4));
                cpa16(bB + off, tb + (size_t)n * 64 + sub * 8);
            }
        }
        cpa_commit();
    };

    float acc[2][4][4];
    #pragma unroll
    for (int mt = 0; mt < 2; ++mt)
        #pragma unroll
        for (int nt = 0; nt < 4; ++nt)
            #pragma unroll
            for (int q = 0; q < 4; ++q) acc[mt][nt][q] = 0.f;

    // ldmatrix lane address components
    const int s7 = lane & 7;
    const int rowA = warpRow + s7 + ((lane >> 3) & 1) * 8;
    const int uA   = lane >> 4;
    const int rowB = warpCol + s7 + (lane >> 4) * 8;
    const int uB   = (lane >> 3) & 1;

    issue(0);
    issue(1);

    for (int s = 0; s < CH; ++s) {
        if (s + 2 < CH)      { issue(s + 2); cpa_wait2(); }
        else if (s + 1 < CH) cpa_wait1();
        else                 cpa_wait0();
        __syncthreads();

        const uint32_t aB = tile0 + (uint32_t)(s % 3) * 32768u;
        const uint32_t bB = aB + 16384u;
        const uint32_t pa0 = aB + ((uint32_t)rowA << 7);
        const uint32_t pa1 = aB + ((uint32_t)(rowA + 16) << 7);

        #pragma unroll
        for (int ks = 0; ks < 4; ++ks) {
            const int u0 = ks * 2;
            uint32_t a[2][4];
            const uint32_t aoff = (uint32_t)(((u0 + uA) ^ s7) << 4);
            ldsm4(a[0], pa0 + aoff);
            ldsm4(a[1], pa1 + aoff);
            const uint32_t boff = (uint32_t)(((u0 + uB) ^ s7) << 4);
            #pragma unroll
            for (int p = 0; p < 2; ++p) {
                uint32_t bfr[4];
                ldsm4(bfr, bB + ((uint32_t)(rowB + p * 16) << 7) + boff);
                mma16(acc[0][2 * p],     a[0], &bfr[0]);
                mma16(acc[0][2 * p + 1], a[0], &bfr[2]);
                mma16(acc[1][2 * p],     a[1], &bfr[0]);
                mma16(acc[1][2 * p + 1], a[1], &bfr[2]);
            }
        }
        __syncthreads();
    }

    // epilogue
    #pragma unroll
    for (int mt = 0; mt < 2; ++mt) {
        int r0 = row0 + warpRow + mt * 16 + g;
        #pragma unroll
        for (int nt = 0; nt < 4; ++nt) {
            int col = warpCol + nt * 8 + 2 * tig;
            if (OUTH) {
                __half* dst = (__half*)dstv;
                if (r0 < NV)
                    *(__half2*)(dst + (size_t)r0 * CB + col) =
                        __floats2half2_rn(acc[mt][nt][0], acc[mt][nt][1]);
                if (r0 + 8 < NV)
                    *(__half2*)(dst + (size_t)(r0 + 8) * CB + col) =
                        __floats2half2_rn(acc[mt][nt][2], acc[mt][nt][3]);
            } else {
                float* dst = (float*)dstv;
                if (r0 < NV)
                    *(float2*)(dst + (size_t)r0 * CB + col) =
                        make_float2(acc[mt][nt][0], acc[mt][nt][1]);
                if (r0 + 8 < NV)
                    *(float2*)(dst + (size_t)(r0 + 8) * CB + col) =
                        make_float2(acc[mt][nt][2], acc[mt][nt][3]);
            }
        }
    }
}

// ---------------- launch ----------------
extern "C" void kernel_launch(void* const* d_in, const int* in_sizes, int n_in,
                              void* d_out, int out_size) {
    const float* feats     = (const float*)d_in[0];
    const float* w1        = (const float*)d_in[1];
    const float* w2        = (const float*)d_in[2];
    const float* w_nin     = (const float*)d_in[3];
    const float* bn1_gamma = (const float*)d_in[4];
    const float* bn1_beta  = (const float*)d_in[5];
    const float* bn2_gamma = (const float*)d_in[6];
    const float* bn2_beta  = (const float*)d_in[7];
    const int*   gidx      = (const int*)d_in[8];
    const int*   sidx      = (const int*)d_in[9];
    float*       out       = (float*)d_out;

    const int dynsm = 3 * 32768 + KOFF * 128 * 4;   // 112128 B
    cudaFuncSetAttribute(k_conv<CA, false, true >, cudaFuncAttributeMaxDynamicSharedMemorySize, dynsm);
    cudaFuncSetAttribute(k_conv<CB, true,  false>, cudaFuncAttributeMaxDynamicSharedMemorySize, dynsm);

    __half *f0h, *h1h, *w1h, *w2h, *tb1, *tb2;
    cudaGetSymbolAddress((void**)&f0h, g_f0h);
    cudaGetSymbolAddress((void**)&h1h, g_h1h);
    cudaGetSymbolAddress((void**)&w1h, g_w1h);
    cudaGetSymbolAddress((void**)&w2h, g_w2h);
    cudaGetSymbolAddress((void**)&tb1, g_tb1);
    cudaGetSymbolAddress((void**)&tb2, g_tb2);

    const int grid = (NV + 127) / 128;   // 1563

    k_bn_partial<CA><<<NBLK, 256>>>(feats);
    k_bn_finalize<CA, 0><<<1, 4 * CA>>>(bn1_gamma, bn1_beta);
    k_prep1<<<NB_F0 + NB_W1 + NB_TB + NB_MI + NB_MAP, 256>>>(feats, w1, gidx, sidx);
    // launch slot #4: conv1 (profiled)
    k_conv<CA, false, true><<<grid, 512, dynsm>>>(f0h, w1h, tb1, h1h);
    k_bn_partial_h<<<NBLK, 256>>>(h1h);
    k_bn_finalize<CB, 1><<<1, 4 * CB>>>(bn2_gamma, bn2_beta);
    k_prep2<<<NB_W2 + NB_TB + 32, 256>>>(w2, w_nin);
    k_conv<CB, true, false><<<grid, 512, dynsm>>>(h1h, w2h, tb2, out);
}